// round 1
// baseline (speedup 1.0000x reference)
#include <cuda_runtime.h>
#include <cstdint>

#define INV_SQRT2 0.7071067811865476f

// x: (B=64, S=4096, F=256) fp32, contiguous.
// out: (B, S/2, 2F) with out[b,s2,2f]   = (x[b,2s2,f] + x[b,2s2+1,f]) * INV_SQRT2
//                        out[b,s2,2f+1] = (x[b,2s2,f] - x[b,2s2+1,f]) * INV_SQRT2
//
// Vectorized: thread t handles 4 consecutive f of one (b,s2) pair.
//   pairs P = B*S/2 = 131072; chunks per pair = F/4 = 64.
//   x0 float4 index: p*128 + c        (row 2s2)
//   x1 float4 index: p*128 + 64 + c   (row 2s2+1)
//   out float4 indices: p*128 + 2c, p*128 + 2c + 1  (interleaved pairs, contiguous)

__global__ void __launch_bounds__(256) haar_kernel(const float4* __restrict__ x,
                                                   float4* __restrict__ out,
                                                   int total_chunks)
{
    int tid = blockIdx.x * blockDim.x + threadIdx.x;
    if (tid >= total_chunks) return;

    int p = tid >> 6;        // pair index (b*S/2 + s2)
    int c = tid & 63;        // float4 chunk within the F=256 row

    size_t base = (size_t)p * 128;
    float4 a = x[base + c];          // x0[f..f+3]
    float4 b = x[base + 64 + c];     // x1[f..f+3]

    float4 o0, o1;
    o0.x = (a.x + b.x) * INV_SQRT2;
    o0.y = (a.x - b.x) * INV_SQRT2;
    o0.z = (a.y + b.y) * INV_SQRT2;
    o0.w = (a.y - b.y) * INV_SQRT2;
    o1.x = (a.z + b.z) * INV_SQRT2;
    o1.y = (a.z - b.z) * INV_SQRT2;
    o1.z = (a.w + b.w) * INV_SQRT2;
    o1.w = (a.w - b.w) * INV_SQRT2;

    size_t ob = base + 2 * (size_t)c;
    out[ob]     = o0;
    out[ob + 1] = o1;
}

extern "C" void kernel_launch(void* const* d_in, const int* in_sizes, int n_in,
                              void* d_out, int out_size)
{
    const float4* x = (const float4*)d_in[0];
    float4* out = (float4*)d_out;

    // total elements = 64*4096*256 = 67108864 floats; chunks = /4 per thread,
    // but each thread consumes 8 floats (4 from each of two rows).
    // total_chunks = pairs * 64 = (in_sizes[0] / 512) * 64 = in_sizes[0] / 8
    int total_chunks = in_sizes[0] / 8;

    int threads = 256;
    int blocks = (total_chunks + threads - 1) / threads;
    haar_kernel<<<blocks, threads>>>(x, out, total_chunks);
}

// round 2
// speedup vs baseline: 1.0051x; 1.0051x over previous
#include <cuda_runtime.h>
#include <cstdint>

#define INV_SQRT2 0.7071067811865476f

// x: (B=64, S=4096, F=256) fp32 contiguous.
// out: (B, S/2, 2F): out[b,s2,2f]   = (x[b,2s2,f] + x[b,2s2+1,f]) * INV_SQRT2
//                    out[b,s2,2f+1] = (x[b,2s2,f] - x[b,2s2+1,f]) * INV_SQRT2
//
// Work mapping (store-contiguous version):
//   pair p = b*(S/2)+s2.  Output row = 512 floats = 128 float4 chunks.
//   Thread j in [0,64) of pair p produces output chunks j and j+64.
//     -> STG #1: lanes of a warp write chunks [w*32 .. w*32+31]   (contiguous 512B)
//     -> STG #2: lanes write chunks [w*32+64 .. w*32+95]          (contiguous 512B)
//   Output chunk o holds f = 2o, 2o+1 (sum,diff interleave), so thread j needs
//   float2 #j and #(j+64) from both input rows — four lane-contiguous LDG.64s.
//
//   Input rows as float2: x0 base = p*256, x1 base = p*256 + 128.
//   Output as float4: base = p*128.

__global__ void __launch_bounds__(256) haar_kernel(const float2* __restrict__ x,
                                                   float4* __restrict__ out,
                                                   int total_threads)
{
    int tid = blockIdx.x * blockDim.x + threadIdx.x;
    if (tid >= total_threads) return;

    int p = tid >> 6;        // pair index
    int j = tid & 63;        // thread-within-pair

    size_t xb = (size_t)p * 256;       // float2 base of x0 row
    const float2* x0 = x + xb;
    const float2* x1 = x + xb + 128;

    // Four independent streaming loads (MLP=4), all lane-contiguous.
    float2 a0 = __ldcs(x0 + j);
    float2 b0 = __ldcs(x1 + j);
    float2 a1 = __ldcs(x0 + j + 64);
    float2 b1 = __ldcs(x1 + j + 64);

    float4 o0, o1;
    o0.x = (a0.x + b0.x) * INV_SQRT2;
    o0.y = (a0.x - b0.x) * INV_SQRT2;
    o0.z = (a0.y + b0.y) * INV_SQRT2;
    o0.w = (a0.y - b0.y) * INV_SQRT2;
    o1.x = (a1.x + b1.x) * INV_SQRT2;
    o1.y = (a1.x - b1.x) * INV_SQRT2;
    o1.z = (a1.y + b1.y) * INV_SQRT2;
    o1.w = (a1.y - b1.y) * INV_SQRT2;

    size_t ob = (size_t)p * 128 + j;
    __stcs(out + ob,      o0);   // chunks [j]    — contiguous across warp
    __stcs(out + ob + 64, o1);   // chunks [j+64] — contiguous across warp
}

extern "C" void kernel_launch(void* const* d_in, const int* in_sizes, int n_in,
                              void* d_out, int out_size)
{
    const float2* x = (const float2*)d_in[0];
    float4* out = (float4*)d_out;

    // Each thread consumes 8 input floats -> total threads = n_elems / 8.
    int total_threads = in_sizes[0] / 8;

    int threads = 256;
    int blocks = (total_threads + threads - 1) / threads;
    haar_kernel<<<blocks, threads>>>(x, out, total_threads);
}